// round 8
// baseline (speedup 1.0000x reference)
#include <cuda_runtime.h>
#include <math.h>

// Geometry (fixed by the problem)
#define NPIX   401408        // 32*112*112
#define DIM    256
#define NCLS   4
#define NSUB   2
#define IMG    12544         // 112*112

// d_out layout: nearest_img | proto_logits | proto_target | new_protos
#define OUT_LOGITS  (NPIX * NCLS)                 // 1605632
#define OUT_TARGET  (OUT_LOGITS + NPIX * 8)       // 4816896
#define OUT_PROTOS  (OUT_TARGET + NPIX)           // 5218304

// ---------------- device scratch (no allocation allowed) ----------------
__device__ double        g_s[3][NCLS][NSUB];     // exp-sum reductions per sinkhorn iter
__device__ double        g_alpha[3][NCLS][NSUB]; // row scalings after each iteration
__device__ int           g_Bn[NCLS];             // per-class pixel counts
__device__ float         g_facc[8][DIM];         // masked feature sums [c*2+m][d]
__device__ int           g_cnt[8];               // assignment counts  [c*2+m]
__device__ float         g_protos[8][DIM];       // l2-normalized prototypes, row = k*2+m
__device__ unsigned char g_correct[NPIX];

__device__ __forceinline__ float wsum(float v) {
#pragma unroll
    for (int o = 16; o; o >>= 1) v += __shfl_xor_sync(0xffffffffu, v, o);
    return v;
}
__device__ __forceinline__ double wsumd(double v) {
#pragma unroll
    for (int o = 16; o; o >>= 1) v += __shfl_xor_sync(0xffffffffu, v, o);
    return v;
}
__device__ __forceinline__ int wsumi(int v) {
#pragma unroll
    for (int o = 16; o; o >>= 1) v += __shfl_xor_sync(0xffffffffu, v, o);
    return v;
}

// ---------------- K0: zero scratch + normalize prototypes ----------------
__global__ void k_init(const float* __restrict__ protos) {
    int tid = threadIdx.x;
    if (tid < 24) ((double*)g_s)[tid] = 0.0;
    if (tid < NCLS) g_Bn[tid] = 0;
    if (tid < 8)    g_cnt[tid] = 0;
    for (int t = tid; t < 8 * DIM; t += blockDim.x) ((float*)g_facc)[t] = 0.f;

    int w = tid >> 5, lane = tid & 31;
    float p[8]; float ss = 0.f;
#pragma unroll
    for (int i = 0; i < 8; i++) { p[i] = protos[w * DIM + lane + 32 * i]; ss += p[i] * p[i]; }
    ss = wsum(ss);
    float inv = 1.0f / fmaxf(sqrtf(ss), 1e-12f);
#pragma unroll
    for (int i = 0; i < 8; i++) g_protos[w][lane + 32 * i] = p[i] * inv;
}

// ---------------- K1: main fused pass over out_feat ----------------
__global__ void __launch_bounds__(256) k_main(
    const float* __restrict__ feat_in, const int* __restrict__ label,
    const float* __restrict__ fg, const float* __restrict__ fb,
    const float* __restrict__ mg, const float* __restrict__ mb,
    float* __restrict__ out)
{
    __shared__ float  sprot[8][DIM];
    __shared__ float  smg[4], smb[4];
    __shared__ float  stage[4][32];
    __shared__ double sred[8];
    __shared__ int    sbn[NCLS];

    int tid = threadIdx.x;
    for (int t = tid; t < 8 * DIM; t += 256) ((float*)sprot)[t] = ((const float*)g_protos)[t];
    if (tid < 4) { smg[tid] = mg[tid]; smb[tid] = mb[tid]; sbn[tid] = 0; }
    if (tid < 8) sred[tid] = 0.0;

    int w = tid >> 5, lane = tid & 31;

    // per-lane gamma/beta in registers (indices 4*lane.., 128+4*lane..)
    const float4* fg4 = (const float4*)fg;
    const float4* fb4 = (const float4*)fb;
    float4 ga = fg4[lane], gb = fg4[lane + 32];
    float4 ba = fb4[lane], bb = fb4[lane + 32];
    float g[8]  = {ga.x, ga.y, ga.z, ga.w, gb.x, gb.y, gb.z, gb.w};
    float be[8] = {ba.x, ba.y, ba.z, ba.w, bb.x, bb.y, bb.z, bb.w};
    __syncthreads();

    // per-thread accumulators (only lanes 0-3 ever add)
    double a0 = 0, a1 = 0, a2 = 0, a3 = 0, a4 = 0, a5 = 0, a6 = 0, a7 = 0;
    int n0c = 0, n1c = 0, n2c = 0, n3c = 0;

    float* logits = out + OUT_LOGITS;
    const int nchunks = NPIX / 32;

    for (int chunk = blockIdx.x; chunk < nchunks; chunk += gridDim.x) {
        float dsave[8];
        const float4* row4 = (const float4*)(feat_in + (size_t)(chunk * 32 + w * 4) * DIM);
        float4 va = row4[lane], vb = row4[lane + 32];
#pragma unroll
        for (int p = 0; p < 4; p++) {
            int n = chunk * 32 + w * 4 + p;
            float x[8] = {va.x, va.y, va.z, va.w, vb.x, vb.y, vb.z, vb.w};
            if (p < 3) {                       // prefetch next pixel row
                const float4* nr4 = row4 + (size_t)(p + 1) * (DIM / 4);
                va = nr4[lane]; vb = nr4[lane + 32];
            }
            float s = 0.f, ss = 0.f;
#pragma unroll
            for (int i = 0; i < 8; i++) { s += x[i]; ss += x[i] * x[i]; }
            s = wsum(s); ss = wsum(ss);
            float mu = s * (1.f / DIM);
            float var = ss * (1.f / DIM) - mu * mu;
            float rstd = rsqrtf(var + 1e-5f);
            float nrm = 0.f;
#pragma unroll
            for (int i = 0; i < 8; i++) {
                x[i] = (x[i] - mu) * rstd * g[i] + be[i];
                nrm += x[i] * x[i];
            }
            nrm = wsum(nrm);
            float inv = 1.0f / fmaxf(sqrtf(nrm), 1e-12f);
#pragma unroll
            for (int i = 0; i < 8; i++) x[i] *= inv;

            float dot[8];
#pragma unroll
            for (int j = 0; j < 8; j++) {
                const float4* p4 = (const float4*)sprot[j];
                float4 pa = p4[lane], pb = p4[lane + 32];
                float d = x[0]*pa.x + x[1]*pa.y + x[2]*pa.z + x[3]*pa.w
                        + x[4]*pb.x + x[5]*pb.y + x[6]*pb.z + x[7]*pb.w;
                dot[j] = wsum(d);             // every lane holds the full dot
            }

            // proto_logits[n, m*4+k] = sim[n,m,k] = dot[k*2+m]; lane j writes slot j
            if (lane < 8) {
                int k = lane & 3, m = lane >> 2;
                logits[(size_t)n * 8 + lane] = dot[k * 2 + m];
            }
            // lane p keeps this pixel's dots for the parallel tail
            if (lane == p) {
#pragma unroll
                for (int i = 0; i < 8; i++) dsave[i] = dot[i];
            }
        }

        // tail: lanes 0-3 each handle one pixel concurrently
        if (lane < 4) {
            int n = chunk * 32 + w * 4 + lane;
            float nr[4], no[4];
#pragma unroll
            for (int k = 0; k < 4; k++) nr[k] = fmaxf(dsave[2 * k], dsave[2 * k + 1]);
            float m4 = 0.25f * (nr[0] + nr[1] + nr[2] + nr[3]);
            float v4 = 0.25f * (nr[0]*nr[0] + nr[1]*nr[1] + nr[2]*nr[2] + nr[3]*nr[3]) - m4 * m4;
            float r4 = rsqrtf(v4 + 1e-5f);
#pragma unroll
            for (int k = 0; k < 4; k++) no[k] = (nr[k] - m4) * r4 * smg[k] + smb[k];
            int pred = 0; float best = no[0];
#pragma unroll
            for (int k = 1; k < 4; k++) if (no[k] > best) { best = no[k]; pred = k; }
            int c = label[n];
            g_correct[n] = (unsigned char)(pred == c);
#pragma unroll
            for (int k = 0; k < 4; k++) stage[k][w * 4 + lane] = no[k];

            float d0, d1;
            switch (c) {
                case 0:  d0 = dsave[0]; d1 = dsave[1]; break;
                case 1:  d0 = dsave[2]; d1 = dsave[3]; break;
                case 2:  d0 = dsave[4]; d1 = dsave[5]; break;
                default: d0 = dsave[6]; d1 = dsave[7]; break;
            }
            float e0 = expf(d0 * 20.0f);   // /SK_EPS
            float e1 = expf(d1 * 20.0f);
            switch (c) {
                case 0:  a0 += e0; a1 += e1; n0c++; break;
                case 1:  a2 += e0; a3 += e1; n1c++; break;
                case 2:  a4 += e0; a5 += e1; n2c++; break;
                default: a6 += e0; a7 += e1; n3c++; break;
            }
        }
        __syncthreads();
        // nearest_img[b,k,h,w]: 32-pixel chunks never cross b (32 | 12544)
        if (tid < 128) {
            int k = tid >> 5, i = tid & 31;
            int base = chunk * 32;
            int b = base / IMG;
            int off = base - b * IMG + i;
            out[(size_t)b * 4 * IMG + (size_t)k * IMG + off] = stage[k][i];
        }
        __syncthreads();
    }

    // block-level reduction of exp sums and counts
    a0 = wsumd(a0); a1 = wsumd(a1); a2 = wsumd(a2); a3 = wsumd(a3);
    a4 = wsumd(a4); a5 = wsumd(a5); a6 = wsumd(a6); a7 = wsumd(a7);
    n0c = wsumi(n0c); n1c = wsumi(n1c); n2c = wsumi(n2c); n3c = wsumi(n3c);
    if (lane == 0) {
        atomicAdd(&sred[0], a0); atomicAdd(&sred[1], a1);
        atomicAdd(&sred[2], a2); atomicAdd(&sred[3], a3);
        atomicAdd(&sred[4], a4); atomicAdd(&sred[5], a5);
        atomicAdd(&sred[6], a6); atomicAdd(&sred[7], a7);
        atomicAdd(&sbn[0], n0c); atomicAdd(&sbn[1], n1c);
        atomicAdd(&sbn[2], n2c); atomicAdd(&sbn[3], n3c);
    }
    __syncthreads();
    if (tid < 8) atomicAdd(&((double*)g_s)[tid], sred[tid]);
    if (tid < 4) atomicAdd(&g_Bn[tid], sbn[tid]);
}

// ---------------- K_alpha: row rescale after each iteration ----------------
__global__ void k_alpha(int stage) {
    int c = threadIdx.x;
    if (c >= NCLS) return;
    double s0 = g_s[stage][c][0], s1 = g_s[stage][c][1];
    double ap0, ap1;
    if (stage == 0) {
        double S = s0 + s1;                    // initial L /= max(sum(L),1e-30)
        double a0 = 1.0 / fmax(S, 1e-30);
        ap0 = a0; ap1 = a0;
    } else {
        ap0 = g_alpha[stage - 1][c][0];
        ap1 = g_alpha[stage - 1][c][1];
    }
    g_alpha[stage][c][0] = ap0 / fmax(ap0 * s0, 1e-30) * 0.5;   // /M
    g_alpha[stage][c][1] = ap1 / fmax(ap1 * s1, 1e-30) * 0.5;
}

// ---------------- K_iter: row-sum reductions for sinkhorn iters 2,3 ----------------
__global__ void __launch_bounds__(256) k_iter(
    int stage, const int* __restrict__ label, const float* __restrict__ logits)
{
    __shared__ double sred[8];
    __shared__ double sa1[8], sa2[8], sbnv[NCLS];
    int tid = threadIdx.x;
    if (tid < 8) {
        sred[tid] = 0.0;
        sa1[tid] = ((double*)g_alpha)[tid];          // g_alpha[0]
        sa2[tid] = ((double*)g_alpha)[8 + tid];      // g_alpha[1]
    }
    if (tid < NCLS) sbnv[tid] = fmax((double)g_Bn[tid], 1.0);
    __syncthreads();

    double a0 = 0, a1 = 0, a2 = 0, a3 = 0, a4 = 0, a5 = 0, a6 = 0, a7 = 0;

    int stride = gridDim.x * blockDim.x;
    for (int n = blockIdx.x * blockDim.x + tid; n < NPIX; n += stride) {
        int c = label[n];
        float s0 = logits[(size_t)n * 8 + c];
        float s1 = logits[(size_t)n * 8 + 4 + c];
        double e0 = (double)expf(s0 * 20.0f), e1 = (double)expf(s1 * 20.0f);
        double bn = sbnv[c];
        double t1 = e0 * sa1[2 * c] + e1 * sa1[2 * c + 1];
        double beta = (1.0 / fmax(t1, 1e-30)) / bn;             // beta1
        if (stage == 2) {
            double t2 = e0 * sa2[2 * c] + e1 * sa2[2 * c + 1];
            beta = beta / fmax(beta * t2, 1e-30) / bn;          // beta2
        }
        double v0 = e0 * beta, v1 = e1 * beta;
        switch (c) {
            case 0:  a0 += v0; a1 += v1; break;
            case 1:  a2 += v0; a3 += v1; break;
            case 2:  a4 += v0; a5 += v1; break;
            default: a6 += v0; a7 += v1; break;
        }
    }
    a0 = wsumd(a0); a1 = wsumd(a1); a2 = wsumd(a2); a3 = wsumd(a3);
    a4 = wsumd(a4); a5 = wsumd(a5); a6 = wsumd(a6); a7 = wsumd(a7);
    if ((tid & 31) == 0) {
        atomicAdd(&sred[0], a0); atomicAdd(&sred[1], a1);
        atomicAdd(&sred[2], a2); atomicAdd(&sred[3], a3);
        atomicAdd(&sred[4], a4); atomicAdd(&sred[5], a5);
        atomicAdd(&sred[6], a6); atomicAdd(&sred[7], a7);
    }
    __syncthreads();
    if (tid < 8) atomicAdd(&((double*)g_s)[stage * 8 + tid], sred[tid]);
}

// ---------------- K_target: proto_target = idx + NSUB*c ----------------
__global__ void k_target(const int* __restrict__ label, const float* __restrict__ logits,
                         float* __restrict__ target)
{
    int n = blockIdx.x * blockDim.x + threadIdx.x;
    if (n >= NPIX) return;
    int c = label[n];
    float s0 = logits[(size_t)n * 8 + c];
    float s1 = logits[(size_t)n * 8 + 4 + c];
    double e0 = (double)expf(s0 * 20.0f) * g_alpha[2][c][0];
    double e1 = (double)expf(s1 * 20.0f) * g_alpha[2][c][1];
    int idx = (e1 > e0) ? 1 : 0;                                // argmax, ties -> 0
    target[n] = (float)(idx + 2 * c);
}

// ---------------- K_accum: masked feature sums (only correct pixels) ----------------
__global__ void __launch_bounds__(256) k_accum(
    const float* __restrict__ feat_in, const int* __restrict__ label,
    const float* __restrict__ fg, const float* __restrict__ fb,
    const float* __restrict__ logits)
{
    __shared__ float sfacc[8][DIM];
    __shared__ int   scnt[8];
    int tid = threadIdx.x;
    for (int t = tid; t < 8 * DIM; t += 256) ((float*)sfacc)[t] = 0.f;
    if (tid < 8) scnt[tid] = 0;

    int w = tid >> 5, lane = tid & 31;
    const float4* fg4 = (const float4*)fg;
    const float4* fb4 = (const float4*)fb;
    float4 ga = fg4[lane], gb = fg4[lane + 32];
    float4 ba = fb4[lane], bb = fb4[lane + 32];
    float g[8]  = {ga.x, ga.y, ga.z, ga.w, gb.x, gb.y, gb.z, gb.w};
    float be[8] = {ba.x, ba.y, ba.z, ba.w, bb.x, bb.y, bb.z, bb.w};
    __syncthreads();

    int gw = blockIdx.x * 8 + w;
    int nw = gridDim.x * 8;

    for (int n = gw; n < NPIX; n += nw) {
        if (!g_correct[n]) continue;
        int c = 0, idx = 0;
        if (lane == 0) {
            c = label[n];
            float s0 = logits[(size_t)n * 8 + c];
            float s1 = logits[(size_t)n * 8 + 4 + c];
            double e0 = (double)expf(s0 * 20.0f) * g_alpha[2][c][0];
            double e1 = (double)expf(s1 * 20.0f) * g_alpha[2][c][1];
            idx = (e1 > e0) ? 1 : 0;
        }
        c   = __shfl_sync(0xffffffffu, c, 0);
        idx = __shfl_sync(0xffffffffu, idx, 0);

        const float4* row4 = (const float4*)(feat_in + (size_t)n * DIM);
        float4 va = row4[lane], vb = row4[lane + 32];
        float x[8] = {va.x, va.y, va.z, va.w, vb.x, vb.y, vb.z, vb.w};
        float s = 0.f, ss = 0.f;
#pragma unroll
        for (int i = 0; i < 8; i++) { s += x[i]; ss += x[i] * x[i]; }
        s = wsum(s); ss = wsum(ss);
        float mu = s * (1.f / DIM), var = ss * (1.f / DIM) - mu * mu;
        float rstd = rsqrtf(var + 1e-5f);
        float nrm = 0.f;
#pragma unroll
        for (int i = 0; i < 8; i++) {
            x[i] = (x[i] - mu) * rstd * g[i] + be[i];
            nrm += x[i] * x[i];
        }
        nrm = wsum(nrm);
        float inv = 1.f / fmaxf(sqrtf(nrm), 1e-12f);
        int r = c * 2 + idx;
        // lane i accumulates smem indices 4*lane.., 128+4*lane..
#pragma unroll
        for (int i = 0; i < 4; i++) atomicAdd(&sfacc[r][4 * lane + i], x[i] * inv);
#pragma unroll
        for (int i = 0; i < 4; i++) atomicAdd(&sfacc[r][128 + 4 * lane + i], x[4 + i] * inv);
        if (lane == 0) atomicAdd(&scnt[r], 1);
    }
    __syncthreads();
    for (int t = tid; t < 8 * DIM; t += 256) atomicAdd(&((float*)g_facc)[t], ((float*)sfacc)[t]);
    if (tid < 8) atomicAdd(&g_cnt[tid], scnt[tid]);
}

// ---------------- K_final: EMA update + renormalize prototypes ----------------
__global__ void k_final(float* __restrict__ out) {
    int tid = threadIdx.x;
    int r = tid >> 5, lane = tid & 31;
    float f[8]; float ss = 0.f;
#pragma unroll
    for (int i = 0; i < 8; i++) { f[i] = g_facc[r][lane + 32 * i]; ss += f[i] * f[i]; }
    ss = wsum(ss);
    float inv = 1.f / fmaxf(sqrtf(ss), 1e-12f);
    int c = r >> 1;
    bool cond = ((g_cnt[c * 2] + g_cnt[c * 2 + 1]) > 0) && (g_cnt[r] != 0);
    float u[8]; float ss2 = 0.f;
#pragma unroll
    for (int i = 0; i < 8; i++) {
        float p = g_protos[r][lane + 32 * i];
        u[i] = cond ? (0.999f * p + 0.001f * (f[i] * inv)) : p;
        ss2 += u[i] * u[i];
    }
    ss2 = wsumd(ss2);
    float inv2 = 1.f / fmaxf(sqrtf(ss2), 1e-12f);
    float* np = out + OUT_PROTOS;
#pragma unroll
    for (int i = 0; i < 8; i++) np[r * DIM + lane + 32 * i] = u[i] * inv2;
}

// ---------------- launch ----------------
extern "C" void kernel_launch(void* const* d_in, const int* in_sizes, int n_in,
                              void* d_out, int out_size)
{
    const float* feat   = (const float*)d_in[0];
    const int*   label  = (const int*)  d_in[1];
    const float* protos = (const float*)d_in[2];
    const float* fg     = (const float*)d_in[3];
    const float* fb     = (const float*)d_in[4];
    const float* mg     = (const float*)d_in[5];
    const float* mb     = (const float*)d_in[6];
    float* out = (float*)d_out;

    k_init<<<1, 256>>>(protos);
    k_main<<<1184, 256>>>(feat, label, fg, fb, mg, mb, out);
    k_alpha<<<1, 32>>>(0);
    k_iter<<<1184, 256>>>(1, label, out + OUT_LOGITS);
    k_alpha<<<1, 32>>>(1);
    k_iter<<<1184, 256>>>(2, label, out + OUT_LOGITS);
    k_alpha<<<1, 32>>>(2);
    k_target<<<(NPIX + 255) / 256, 256>>>(label, out + OUT_LOGITS, out + OUT_TARGET);
    k_accum<<<592, 256>>>(feat, label, fg, fb, out + OUT_LOGITS);
    k_final<<<1, 256>>>(out);
}

// round 9
// speedup vs baseline: 1.8864x; 1.8864x over previous
#include <cuda_runtime.h>
#include <math.h>

// Geometry (fixed by the problem)
#define NPIX   401408        // 32*112*112
#define DIM    256
#define NCLS   4
#define NSUB   2
#define IMG    12544         // 112*112
#define NCHUNK (NPIX / 32)   // 12544

// d_out layout: nearest_img | proto_logits | proto_target | new_protos
#define OUT_LOGITS  (NPIX * NCLS)                 // 1605632
#define OUT_TARGET  (OUT_LOGITS + NPIX * 8)       // 4816896
#define OUT_PROTOS  (OUT_TARGET + NPIX)           // 5218304

// ---------------- device scratch (no allocation allowed) ----------------
// Scale-free sinkhorn state: u1 = 1/E, u2 = 1/T2, u3 = 1/T3 (per class, per sub)
__device__ double        g_E[8];                 // Σ e_m per class   [c*2+m]
__device__ double        g_T2[8];                // iter-2 row sums
__device__ double        g_T3[8];                // iter-3 row sums
__device__ float         g_facc[8][DIM];         // masked feature sums [c*2+m][d]
__device__ int           g_cnt[8];               // assignment counts  [c*2+m]
__device__ float         g_protos[8][DIM];       // l2-normalized prototypes, row = k*2+m
__device__ float2        g_e[NPIX];              // (e0, e1) for the pixel's own class
__device__ unsigned char g_code[NPIX];           // bits 0-1: class, bit 2: correct
__device__ unsigned char g_ridx[NPIX];           // c*2+idx if correct else 255

__device__ __forceinline__ float wsum(float v) {
#pragma unroll
    for (int o = 16; o; o >>= 1) v += __shfl_xor_sync(0xffffffffu, v, o);
    return v;
}

// ---------------- K0: zero scratch + normalize prototypes ----------------
__global__ void k_init(const float* __restrict__ protos) {
    int tid = threadIdx.x;
    if (tid < 8)  { g_E[tid] = 0.0; g_T2[tid] = 0.0; g_T3[tid] = 0.0; g_cnt[tid] = 0; }
    for (int t = tid; t < 8 * DIM; t += blockDim.x) ((float*)g_facc)[t] = 0.f;

    int w = tid >> 5, lane = tid & 31;
    float p[8]; float ss = 0.f;
#pragma unroll
    for (int i = 0; i < 8; i++) { p[i] = protos[w * DIM + lane + 32 * i]; ss += p[i] * p[i]; }
    ss = wsum(ss);
    float inv = 1.0f / fmaxf(sqrtf(ss), 1e-12f);
#pragma unroll
    for (int i = 0; i < 8; i++) g_protos[w][lane + 32 * i] = p[i] * inv;
}

// ---------------- K1: main fused pass over out_feat ----------------
__global__ void __launch_bounds__(256) k_main(
    const float* __restrict__ feat_in, const int* __restrict__ label,
    const float* __restrict__ fg, const float* __restrict__ fb,
    const float* __restrict__ mg, const float* __restrict__ mb,
    float* __restrict__ out)
{
    __shared__ float sprot[8][DIM];
    __shared__ float smg[4], smb[4];
    __shared__ float stage[4][32];
    __shared__ float sred[8];

    int tid = threadIdx.x;
    for (int t = tid; t < 8 * DIM; t += 256) ((float*)sprot)[t] = ((const float*)g_protos)[t];
    if (tid < 4) { smg[tid] = mg[tid]; smb[tid] = mb[tid]; }
    if (tid < 8) sred[tid] = 0.f;

    int w = tid >> 5, lane = tid & 31;

    // per-lane gamma/beta in registers (elements 4*lane.. , 128+4*lane..)
    const float4* fg4 = (const float4*)fg;
    const float4* fb4 = (const float4*)fb;
    float4 ga = fg4[lane], gb = fg4[lane + 32];
    float4 ba = fb4[lane], bb = fb4[lane + 32];
    float g[8]  = {ga.x, ga.y, ga.z, ga.w, gb.x, gb.y, gb.z, gb.w};
    float be[8] = {ba.x, ba.y, ba.z, ba.w, bb.x, bb.y, bb.z, bb.w};
    __syncthreads();

    // lane-0 float accumulators for Σ e_m per class
    float f0 = 0.f, f1 = 0.f, f2 = 0.f, f3 = 0.f, f4 = 0.f, f5 = 0.f, f6 = 0.f, f7 = 0.f;

    float* logits = out + OUT_LOGITS;

    for (int chunk = blockIdx.x; chunk < NCHUNK; chunk += gridDim.x) {
#pragma unroll 1
        for (int p = 0; p < 4; p++) {
            int n = chunk * 32 + w * 4 + p;
            const float4* row4 = (const float4*)(feat_in + (size_t)n * DIM);
            float4 va = row4[lane], vb = row4[lane + 32];
            float x[8] = {va.x, va.y, va.z, va.w, vb.x, vb.y, vb.z, vb.w};
            float s = 0.f, ss = 0.f;
#pragma unroll
            for (int i = 0; i < 8; i++) { s += x[i]; ss += x[i] * x[i]; }
            s = wsum(s); ss = wsum(ss);
            float mu = s * (1.f / DIM);
            float var = ss * (1.f / DIM) - mu * mu;
            float rstd = rsqrtf(var + 1e-5f);
            float nrm = 0.f;
#pragma unroll
            for (int i = 0; i < 8; i++) {
                x[i] = (x[i] - mu) * rstd * g[i] + be[i];
                nrm += x[i] * x[i];
            }
            nrm = wsum(nrm);
            float inv = 1.0f / fmaxf(sqrtf(nrm), 1e-12f);
#pragma unroll
            for (int i = 0; i < 8; i++) x[i] *= inv;

            float dot[8];
#pragma unroll
            for (int j = 0; j < 8; j++) {
                const float4* p4 = (const float4*)sprot[j];
                float4 pa = p4[lane], pb = p4[lane + 32];
                float d = x[0]*pa.x + x[1]*pa.y + x[2]*pa.z + x[3]*pa.w
                        + x[4]*pb.x + x[5]*pb.y + x[6]*pb.z + x[7]*pb.w;
                dot[j] = wsum(d);             // every lane holds the full dot
            }

            // proto_logits[n, m*4+k] = dot[k*2+m]; lane j writes slot j
            if (lane < 8) {
                int k = lane & 3, m = lane >> 2;
                logits[(size_t)n * 8 + lane] = dot[k * 2 + m];
            }

            if (lane == 0) {
                float nr[4], no[4];
#pragma unroll
                for (int k = 0; k < 4; k++) nr[k] = fmaxf(dot[2 * k], dot[2 * k + 1]);
                float m4 = 0.25f * (nr[0] + nr[1] + nr[2] + nr[3]);
                float v4 = 0.25f * (nr[0]*nr[0] + nr[1]*nr[1] + nr[2]*nr[2] + nr[3]*nr[3]) - m4 * m4;
                float r4 = rsqrtf(v4 + 1e-5f);
#pragma unroll
                for (int k = 0; k < 4; k++) no[k] = (nr[k] - m4) * r4 * smg[k] + smb[k];
                int pred = 0; float best = no[0];
#pragma unroll
                for (int k = 1; k < 4; k++) if (no[k] > best) { best = no[k]; pred = k; }
                int c = label[n];
#pragma unroll
                for (int k = 0; k < 4; k++) stage[k][w * 4 + p] = no[k];

                float d0, d1;
                switch (c) {
                    case 0:  d0 = dot[0]; d1 = dot[1]; break;
                    case 1:  d0 = dot[2]; d1 = dot[3]; break;
                    case 2:  d0 = dot[4]; d1 = dot[5]; break;
                    default: d0 = dot[6]; d1 = dot[7]; break;
                }
                float e0 = expf(d0 * 20.0f);   // /SK_EPS
                float e1 = expf(d1 * 20.0f);
                g_e[n] = make_float2(e0, e1);
                g_code[n] = (unsigned char)(c | ((pred == c) << 2));
                switch (c) {
                    case 0:  f0 += e0; f1 += e1; break;
                    case 1:  f2 += e0; f3 += e1; break;
                    case 2:  f4 += e0; f5 += e1; break;
                    default: f6 += e0; f7 += e1; break;
                }
            }
        }
        __syncthreads();
        // nearest_img[b,k,h,w]: 32-pixel chunks never cross b (32 | 12544)
        if (tid < 128) {
            int k = tid >> 5, i = tid & 31;
            int base = chunk * 32;
            int b = base / IMG;
            int off = base - b * IMG + i;
            out[(size_t)b * 4 * IMG + (size_t)k * IMG + off] = stage[k][i];
        }
        __syncthreads();
    }

    if (lane == 0) {
        atomicAdd(&sred[0], f0); atomicAdd(&sred[1], f1);
        atomicAdd(&sred[2], f2); atomicAdd(&sred[3], f3);
        atomicAdd(&sred[4], f4); atomicAdd(&sred[5], f5);
        atomicAdd(&sred[6], f6); atomicAdd(&sred[7], f7);
    }
    __syncthreads();
    if (tid < 8) atomicAdd(&g_E[tid], (double)sred[tid]);
}

// ---------------- K_R: sinkhorn row-sum reduction (stage 1 -> T2, stage 2 -> T3) ----------------
__global__ void __launch_bounds__(256) k_R(int stage) {
    __shared__ float sw[8];
    __shared__ float sred[8];
    int tid = threadIdx.x;
    if (tid < 8) {
        double src = (stage == 1) ? g_E[tid] : g_T2[tid];
        sw[tid] = (float)(1.0 / fmax(src, 1e-300));
        sred[tid] = 0.f;
    }
    __syncthreads();

    float f0 = 0.f, f1 = 0.f, f2 = 0.f, f3 = 0.f, f4 = 0.f, f5 = 0.f, f6 = 0.f, f7 = 0.f;

    int stride = gridDim.x * blockDim.x;
    for (int n = blockIdx.x * blockDim.x + tid; n < NPIX; n += stride) {
        int c = g_code[n] & 3;
        float2 e = g_e[n];
        float den = e.x * sw[2 * c] + e.y * sw[2 * c + 1];
        float ib = 1.0f / den;
        float v0 = e.x * ib, v1 = e.y * ib;
        switch (c) {
            case 0:  f0 += v0; f1 += v1; break;
            case 1:  f2 += v0; f3 += v1; break;
            case 2:  f4 += v0; f5 += v1; break;
            default: f6 += v0; f7 += v1; break;
        }
    }
    f0 = wsum(f0); f1 = wsum(f1); f2 = wsum(f2); f3 = wsum(f3);
    f4 = wsum(f4); f5 = wsum(f5); f6 = wsum(f6); f7 = wsum(f7);
    if ((tid & 31) == 0) {
        atomicAdd(&sred[0], f0); atomicAdd(&sred[1], f1);
        atomicAdd(&sred[2], f2); atomicAdd(&sred[3], f3);
        atomicAdd(&sred[4], f4); atomicAdd(&sred[5], f5);
        atomicAdd(&sred[6], f6); atomicAdd(&sred[7], f7);
    }
    __syncthreads();
    if (tid < 8) {
        double* dst = (stage == 1) ? g_T2 : g_T3;
        atomicAdd(&dst[tid], (double)sred[tid]);
    }
}

// ---------------- K_target: proto_target + final assignment byte ----------------
__global__ void k_target(float* __restrict__ target) {
    __shared__ float sw[8];
    int tid = threadIdx.x;
    if (tid < 8) sw[tid] = (float)(1.0 / fmax(g_T3[tid], 1e-300));
    __syncthreads();
    int n = blockIdx.x * blockDim.x + tid;
    if (n >= NPIX) return;
    unsigned char code = g_code[n];
    int c = code & 3;
    float2 e = g_e[n];
    int idx = (e.y * sw[2 * c + 1] > e.x * sw[2 * c]) ? 1 : 0;   // ties -> 0
    target[n] = (float)(idx + 2 * c);
    g_ridx[n] = (code & 4) ? (unsigned char)(c * 2 + idx) : (unsigned char)255;
}

// ---------------- K_accum: masked feature sums (only correct pixels) ----------------
__global__ void __launch_bounds__(256) k_accum(
    const float* __restrict__ feat_in,
    const float* __restrict__ fg, const float* __restrict__ fb)
{
    __shared__ float sfacc[8][DIM];
    __shared__ int   scnt[8];
    int tid = threadIdx.x;
    for (int t = tid; t < 8 * DIM; t += 256) ((float*)sfacc)[t] = 0.f;
    if (tid < 8) scnt[tid] = 0;

    int w = tid >> 5, lane = tid & 31;
    const float4* fg4 = (const float4*)fg;
    const float4* fb4 = (const float4*)fb;
    float4 ga = fg4[lane], gb = fg4[lane + 32];
    float4 ba = fb4[lane], bb = fb4[lane + 32];
    float g[8]  = {ga.x, ga.y, ga.z, ga.w, gb.x, gb.y, gb.z, gb.w};
    float be[8] = {ba.x, ba.y, ba.z, ba.w, bb.x, bb.y, bb.z, bb.w};
    __syncthreads();

    for (int chunk = blockIdx.x * 8 + w; chunk < NCHUNK; chunk += gridDim.x * 8) {
        int n0 = chunk * 32;
        int r = g_ridx[n0 + lane];
        unsigned mask = __ballot_sync(0xffffffffu, r != 255);
        while (mask) {
            int j = __ffs(mask) - 1;
            mask &= mask - 1;
            int rr = __shfl_sync(0xffffffffu, r, j);
            int n = n0 + j;

            const float4* row4 = (const float4*)(feat_in + (size_t)n * DIM);
            float4 va = row4[lane], vb = row4[lane + 32];
            float x[8] = {va.x, va.y, va.z, va.w, vb.x, vb.y, vb.z, vb.w};
            float s = 0.f, ss = 0.f;
#pragma unroll
            for (int i = 0; i < 8; i++) { s += x[i]; ss += x[i] * x[i]; }
            s = wsum(s); ss = wsum(ss);
            float mu = s * (1.f / DIM), var = ss * (1.f / DIM) - mu * mu;
            float rstd = rsqrtf(var + 1e-5f);
            float nrm = 0.f;
#pragma unroll
            for (int i = 0; i < 8; i++) {
                x[i] = (x[i] - mu) * rstd * g[i] + be[i];
                nrm += x[i] * x[i];
            }
            nrm = wsum(nrm);
            float inv = 1.f / fmaxf(sqrtf(nrm), 1e-12f);
#pragma unroll
            for (int i = 0; i < 4; i++) atomicAdd(&sfacc[rr][4 * lane + i], x[i] * inv);
#pragma unroll
            for (int i = 0; i < 4; i++) atomicAdd(&sfacc[rr][128 + 4 * lane + i], x[4 + i] * inv);
            if (lane == 0) atomicAdd(&scnt[rr], 1);
        }
    }
    __syncthreads();
    for (int t = tid; t < 8 * DIM; t += 256) atomicAdd(&((float*)g_facc)[t], ((float*)sfacc)[t]);
    if (tid < 8) atomicAdd(&g_cnt[tid], scnt[tid]);
}

// ---------------- K_final: EMA update + renormalize prototypes ----------------
__global__ void k_final(float* __restrict__ out) {
    int tid = threadIdx.x;
    int r = tid >> 5, lane = tid & 31;
    float f[8]; float ss = 0.f;
#pragma unroll
    for (int i = 0; i < 8; i++) { f[i] = g_facc[r][lane + 32 * i]; ss += f[i] * f[i]; }
    ss = wsum(ss);
    float inv = 1.f / fmaxf(sqrtf(ss), 1e-12f);
    int c = r >> 1;
    bool cond = ((g_cnt[c * 2] + g_cnt[c * 2 + 1]) > 0) && (g_cnt[r] != 0);
    float u[8]; float ss2 = 0.f;
#pragma unroll
    for (int i = 0; i < 8; i++) {
        float p = g_protos[r][lane + 32 * i];
        u[i] = cond ? (0.999f * p + 0.001f * (f[i] * inv)) : p;
        ss2 += u[i] * u[i];
    }
    ss2 = wsum(ss2);
    float inv2 = 1.f / fmaxf(sqrtf(ss2), 1e-12f);
    float* np = out + OUT_PROTOS;
#pragma unroll
    for (int i = 0; i < 8; i++) np[r * DIM + lane + 32 * i] = u[i] * inv2;
}

// ---------------- launch ----------------
extern "C" void kernel_launch(void* const* d_in, const int* in_sizes, int n_in,
                              void* d_out, int out_size)
{
    const float* feat   = (const float*)d_in[0];
    const int*   label  = (const int*)  d_in[1];
    const float* protos = (const float*)d_in[2];
    const float* fg     = (const float*)d_in[3];
    const float* fb     = (const float*)d_in[4];
    const float* mg     = (const float*)d_in[5];
    const float* mb     = (const float*)d_in[6];
    float* out = (float*)d_out;

    k_init<<<1, 256>>>(protos);
    k_main<<<1184, 256>>>(feat, label, fg, fb, mg, mb, out);
    k_R<<<1184, 256>>>(1);
    k_R<<<1184, 256>>>(2);
    k_target<<<NPIX / 256, 256>>>(out + OUT_TARGET);
    k_accum<<<1184, 256>>>(feat, fg, fb);
    k_final<<<1, 256>>>(out);
}

// round 10
// speedup vs baseline: 2.0563x; 1.0900x over previous
#include <cuda_runtime.h>
#include <math.h>

// Geometry (fixed by the problem)
#define NPIX   401408        // 32*112*112
#define DIM    256
#define NCLS   4
#define NSUB   2
#define IMG    12544         // 112*112
#define NCHUNK (NPIX / 32)   // 12544

// d_out layout: nearest_img | proto_logits | proto_target | new_protos
#define OUT_LOGITS  (NPIX * NCLS)                 // 1605632
#define OUT_TARGET  (OUT_LOGITS + NPIX * 8)       // 4816896
#define OUT_PROTOS  (OUT_TARGET + NPIX)           // 5218304

#define FULLW 0xffffffffu

// ---------------- device scratch (no allocation allowed) ----------------
__device__ double        g_E[8];                 // Σ e_m per class   [c*2+m]
__device__ double        g_T2[8];                // iter-2 row sums
__device__ double        g_T3[8];                // iter-3 row sums
__device__ float         g_facc[8][DIM];         // masked feature sums [c*2+m][d]
__device__ int           g_cnt[8];               // assignment counts  [c*2+m]
__device__ float         g_protos[8][DIM];       // l2-normalized prototypes, row = k*2+m
__device__ float2        g_e[NPIX];              // (e0, e1) for the pixel's own class
__device__ unsigned char g_code[NPIX];           // bits 0-1: class, bit 2: correct
__device__ unsigned char g_ridx[NPIX];           // c*2+idx if correct else 255

__device__ __forceinline__ float wsum(float v) {
#pragma unroll
    for (int o = 16; o; o >>= 1) v += __shfl_xor_sync(FULLW, v, o);
    return v;
}

// value-folding reduction step: combines (a,b) across lane-pairs at `off`;
// result lands in a (lanes with bit set hold b's sum line, others a's).
__device__ __forceinline__ void fold2(float& a, float b, int off, int lane) {
    bool hi = (lane & off) != 0;
    float keep = hi ? b : a;
    float send = hi ? a : b;
    a = keep + __shfl_xor_sync(FULLW, send, off);
}

// ---------------- K0: zero scratch + normalize prototypes ----------------
__global__ void k_init(const float* __restrict__ protos) {
    int tid = threadIdx.x;
    if (tid < 8)  { g_E[tid] = 0.0; g_T2[tid] = 0.0; g_T3[tid] = 0.0; g_cnt[tid] = 0; }
    for (int t = tid; t < 8 * DIM; t += blockDim.x) ((float*)g_facc)[t] = 0.f;

    int w = tid >> 5, lane = tid & 31;
    float p[8]; float ss = 0.f;
#pragma unroll
    for (int i = 0; i < 8; i++) { p[i] = protos[w * DIM + lane + 32 * i]; ss += p[i] * p[i]; }
    ss = wsum(ss);
    float inv = 1.0f / fmaxf(sqrtf(ss), 1e-12f);
#pragma unroll
    for (int i = 0; i < 8; i++) g_protos[w][lane + 32 * i] = p[i] * inv;
}

// ---------------- K1: main fused pass over out_feat ----------------
__global__ void __launch_bounds__(256) k_main(
    const float* __restrict__ feat_in, const int* __restrict__ label,
    const float* __restrict__ fg, const float* __restrict__ fb,
    const float* __restrict__ mg, const float* __restrict__ mb,
    float* __restrict__ out)
{
    __shared__ float sprot[8][DIM];
    __shared__ float smg[4], smb[4];
    __shared__ float stage[4][32];
    __shared__ float sred[8];

    int tid = threadIdx.x;
    for (int t = tid; t < 8 * DIM; t += 256) ((float*)sprot)[t] = ((const float*)g_protos)[t];
    if (tid < 4) { smg[tid] = mg[tid]; smb[tid] = mb[tid]; }
    if (tid < 8) sred[tid] = 0.f;

    int w = tid >> 5, lane = tid & 31;

    const float4* fg4 = (const float4*)fg;
    const float4* fb4 = (const float4*)fb;
    float4 ga = fg4[lane], gb = fg4[lane + 32];
    float4 ba = fb4[lane], bb = fb4[lane + 32];
    float g[8]  = {ga.x, ga.y, ga.z, ga.w, gb.x, gb.y, gb.z, gb.w};
    float be[8] = {ba.x, ba.y, ba.z, ba.w, bb.x, bb.y, bb.z, bb.w};
    __syncthreads();

    // lane-0 accumulators for Σ e_m per class
    float f0 = 0.f, f1 = 0.f, f2 = 0.f, f3 = 0.f, f4 = 0.f, f5 = 0.f, f6 = 0.f, f7 = 0.f;

    float* logits = out + OUT_LOGITS;

    for (int chunk = blockIdx.x; chunk < NCHUNK; chunk += gridDim.x) {
#pragma unroll 1
        for (int p = 0; p < 4; p++) {
            int n = chunk * 32 + w * 4 + p;
            const float4* row4 = (const float4*)(feat_in + (size_t)n * DIM);
            float4 va = row4[lane], vb = row4[lane + 32];
            float x[8] = {va.x, va.y, va.z, va.w, vb.x, vb.y, vb.z, vb.w};
            float s = 0.f, ss = 0.f;
#pragma unroll
            for (int i = 0; i < 8; i++) { s += x[i]; ss += x[i] * x[i]; }
            // folded (s,ss) reduction: 7 shuffles
            {
                float v = (lane & 16) ? ss : s;
                float o = (lane & 16) ? s : ss;
                v += __shfl_xor_sync(FULLW, o, 16);
                v += __shfl_xor_sync(FULLW, v, 8);
                v += __shfl_xor_sync(FULLW, v, 4);
                v += __shfl_xor_sync(FULLW, v, 2);
                v += __shfl_xor_sync(FULLW, v, 1);
                s  = __shfl_sync(FULLW, v, lane & 15);
                ss = __shfl_sync(FULLW, v, (lane & 15) | 16);
            }
            float mu = s * (1.f / DIM);
            float var = ss * (1.f / DIM) - mu * mu;
            float rstd = rsqrtf(var + 1e-5f);
            float nrm = 0.f;
#pragma unroll
            for (int i = 0; i < 8; i++) {
                x[i] = (x[i] - mu) * rstd * g[i] + be[i];
                nrm += x[i] * x[i];
            }
            nrm = wsum(nrm);
            float inv = 1.0f / fmaxf(sqrtf(nrm), 1e-12f);
#pragma unroll
            for (int i = 0; i < 8; i++) x[i] *= inv;

            // per-lane partial dots
            float d0, d1, d2, d3, d4, d5, d6, d7;
            {
                float dd[8];
#pragma unroll
                for (int j = 0; j < 8; j++) {
                    const float4* p4 = (const float4*)sprot[j];
                    float4 pa = p4[lane], pb = p4[lane + 32];
                    dd[j] = x[0]*pa.x + x[1]*pa.y + x[2]*pa.z + x[3]*pa.w
                          + x[4]*pb.x + x[5]*pb.y + x[6]*pb.z + x[7]*pb.w;
                }
                d0 = dd[0]; d1 = dd[1]; d2 = dd[2]; d3 = dd[3];
                d4 = dd[4]; d5 = dd[5]; d6 = dd[6]; d7 = dd[7];
            }
            // folded 8-value reduction: lane 4j ends with full dot[j]
            fold2(d0, d4, 16, lane);
            fold2(d1, d5, 16, lane);
            fold2(d2, d6, 16, lane);
            fold2(d3, d7, 16, lane);
            fold2(d0, d2, 8, lane);
            fold2(d1, d3, 8, lane);
            fold2(d0, d1, 4, lane);
            d0 += __shfl_xor_sync(FULLW, d0, 2);
            d0 += __shfl_xor_sync(FULLW, d0, 1);

            // direct permuted logits store: lane 4j holds dot j = dot[k*2+m],
            // slot = m*4+k with k=j>>1, m=j&1
            if ((lane & 3) == 0) {
                int j = lane >> 2;
                int slot = ((j & 1) << 2) | (j >> 1);
                logits[(size_t)n * 8 + slot] = d0;
            }

            // gather all 8 dots to every lane (named scalars, static indexing)
            float dt0 = __shfl_sync(FULLW, d0, 0);
            float dt1 = __shfl_sync(FULLW, d0, 4);
            float dt2 = __shfl_sync(FULLW, d0, 8);
            float dt3 = __shfl_sync(FULLW, d0, 12);
            float dt4 = __shfl_sync(FULLW, d0, 16);
            float dt5 = __shfl_sync(FULLW, d0, 20);
            float dt6 = __shfl_sync(FULLW, d0, 24);
            float dt7 = __shfl_sync(FULLW, d0, 28);

            // tail on ALL lanes (redundant, divergence-free)
            float nr0 = fmaxf(dt0, dt1), nr1 = fmaxf(dt2, dt3);
            float nr2 = fmaxf(dt4, dt5), nr3 = fmaxf(dt6, dt7);
            float m4 = 0.25f * (nr0 + nr1 + nr2 + nr3);
            float v4 = 0.25f * (nr0*nr0 + nr1*nr1 + nr2*nr2 + nr3*nr3) - m4 * m4;
            float r4 = rsqrtf(v4 + 1e-5f);
            float no0 = (nr0 - m4) * r4 * smg[0] + smb[0];
            float no1 = (nr1 - m4) * r4 * smg[1] + smb[1];
            float no2 = (nr2 - m4) * r4 * smg[2] + smb[2];
            float no3 = (nr3 - m4) * r4 * smg[3] + smb[3];
            int pred = 0; float best = no0;
            if (no1 > best) { best = no1; pred = 1; }
            if (no2 > best) { best = no2; pred = 2; }
            if (no3 > best) { best = no3; pred = 3; }
            int c = label[n];
            float e0d = (c == 0) ? dt0 : (c == 1) ? dt2 : (c == 2) ? dt4 : dt6;
            float e1d = (c == 0) ? dt1 : (c == 1) ? dt3 : (c == 2) ? dt5 : dt7;
            float e0 = expf(e0d * 20.0f);   // /SK_EPS
            float e1 = expf(e1d * 20.0f);

            if (lane == 0) {
                g_e[n] = make_float2(e0, e1);
                g_code[n] = (unsigned char)(c | ((pred == c) << 2));
                stage[0][w * 4 + p] = no0;
                stage[1][w * 4 + p] = no1;
                stage[2][w * 4 + p] = no2;
                stage[3][w * 4 + p] = no3;
                switch (c) {
                    case 0:  f0 += e0; f1 += e1; break;
                    case 1:  f2 += e0; f3 += e1; break;
                    case 2:  f4 += e0; f5 += e1; break;
                    default: f6 += e0; f7 += e1; break;
                }
            }
        }
        __syncthreads();
        // nearest_img[b,k,h,w]: 32-pixel chunks never cross b (32 | 12544)
        if (tid < 128) {
            int k = tid >> 5, i = tid & 31;
            int base = chunk * 32;
            int b = base / IMG;
            int off = base - b * IMG + i;
            out[(size_t)b * 4 * IMG + (size_t)k * IMG + off] = stage[k][i];
        }
        __syncthreads();
    }

    if (lane == 0) {
        atomicAdd(&sred[0], f0); atomicAdd(&sred[1], f1);
        atomicAdd(&sred[2], f2); atomicAdd(&sred[3], f3);
        atomicAdd(&sred[4], f4); atomicAdd(&sred[5], f5);
        atomicAdd(&sred[6], f6); atomicAdd(&sred[7], f7);
    }
    __syncthreads();
    if (tid < 8) atomicAdd(&g_E[tid], (double)sred[tid]);
}

// ---------------- K_R: sinkhorn row-sum reduction (stage 1 -> T2, stage 2 -> T3) ----------------
__global__ void __launch_bounds__(256) k_R(int stage) {
    __shared__ float sw[8];
    __shared__ float sred[8];
    int tid = threadIdx.x;
    if (tid < 8) {
        double src = (stage == 1) ? g_E[tid] : g_T2[tid];
        sw[tid] = (float)(1.0 / fmax(src, 1e-300));
        sred[tid] = 0.f;
    }
    __syncthreads();

    float f0 = 0.f, f1 = 0.f, f2 = 0.f, f3 = 0.f, f4 = 0.f, f5 = 0.f, f6 = 0.f, f7 = 0.f;

    int stride = gridDim.x * blockDim.x;
    for (int n = blockIdx.x * blockDim.x + tid; n < NPIX; n += stride) {
        int c = g_code[n] & 3;
        float2 e = g_e[n];
        float den = e.x * sw[2 * c] + e.y * sw[2 * c + 1];
        float ib = 1.0f / den;
        float v0 = e.x * ib, v1 = e.y * ib;
        switch (c) {
            case 0:  f0 += v0; f1 += v1; break;
            case 1:  f2 += v0; f3 += v1; break;
            case 2:  f4 += v0; f5 += v1; break;
            default: f6 += v0; f7 += v1; break;
        }
    }
    f0 = wsum(f0); f1 = wsum(f1); f2 = wsum(f2); f3 = wsum(f3);
    f4 = wsum(f4); f5 = wsum(f5); f6 = wsum(f6); f7 = wsum(f7);
    if ((tid & 31) == 0) {
        atomicAdd(&sred[0], f0); atomicAdd(&sred[1], f1);
        atomicAdd(&sred[2], f2); atomicAdd(&sred[3], f3);
        atomicAdd(&sred[4], f4); atomicAdd(&sred[5], f5);
        atomicAdd(&sred[6], f6); atomicAdd(&sred[7], f7);
    }
    __syncthreads();
    if (tid < 8) {
        double* dst = (stage == 1) ? g_T2 : g_T3;
        atomicAdd(&dst[tid], (double)sred[tid]);
    }
}

// ---------------- K_target: proto_target + final assignment byte ----------------
__global__ void k_target(float* __restrict__ target) {
    __shared__ float sw[8];
    int tid = threadIdx.x;
    if (tid < 8) sw[tid] = (float)(1.0 / fmax(g_T3[tid], 1e-300));
    __syncthreads();
    int n = blockIdx.x * blockDim.x + tid;
    if (n >= NPIX) return;
    unsigned char code = g_code[n];
    int c = code & 3;
    float2 e = g_e[n];
    int idx = (e.y * sw[2 * c + 1] > e.x * sw[2 * c]) ? 1 : 0;   // ties -> 0
    target[n] = (float)(idx + 2 * c);
    g_ridx[n] = (code & 4) ? (unsigned char)(c * 2 + idx) : (unsigned char)255;
}

// ---------------- K_accum: masked feature sums (only correct pixels) ----------------
__global__ void __launch_bounds__(256) k_accum(
    const float* __restrict__ feat_in,
    const float* __restrict__ fg, const float* __restrict__ fb)
{
    __shared__ float sfacc[8][DIM];
    __shared__ int   scnt[8];
    int tid = threadIdx.x;
    for (int t = tid; t < 8 * DIM; t += 256) ((float*)sfacc)[t] = 0.f;
    if (tid < 8) scnt[tid] = 0;

    int w = tid >> 5, lane = tid & 31;
    const float4* fg4 = (const float4*)fg;
    const float4* fb4 = (const float4*)fb;
    float4 ga = fg4[lane], gb = fg4[lane + 32];
    float4 ba = fb4[lane], bb = fb4[lane + 32];
    float g[8]  = {ga.x, ga.y, ga.z, ga.w, gb.x, gb.y, gb.z, gb.w};
    float be[8] = {ba.x, ba.y, ba.z, ba.w, bb.x, bb.y, bb.z, bb.w};
    __syncthreads();

    for (int chunk = blockIdx.x * 8 + w; chunk < NCHUNK; chunk += gridDim.x * 8) {
        int n0 = chunk * 32;
        int r = g_ridx[n0 + lane];
        unsigned mask = __ballot_sync(FULLW, r != 255);
        while (mask) {
            int j = __ffs(mask) - 1;
            mask &= mask - 1;
            int rr = __shfl_sync(FULLW, r, j);
            int n = n0 + j;

            const float4* row4 = (const float4*)(feat_in + (size_t)n * DIM);
            float4 va = row4[lane], vb = row4[lane + 32];
            float x[8] = {va.x, va.y, va.z, va.w, vb.x, vb.y, vb.z, vb.w};
            float s = 0.f, ss = 0.f;
#pragma unroll
            for (int i = 0; i < 8; i++) { s += x[i]; ss += x[i] * x[i]; }
            {
                float v = (lane & 16) ? ss : s;
                float o = (lane & 16) ? s : ss;
                v += __shfl_xor_sync(FULLW, o, 16);
                v += __shfl_xor_sync(FULLW, v, 8);
                v += __shfl_xor_sync(FULLW, v, 4);
                v += __shfl_xor_sync(FULLW, v, 2);
                v += __shfl_xor_sync(FULLW, v, 1);
                s  = __shfl_sync(FULLW, v, lane & 15);
                ss = __shfl_sync(FULLW, v, (lane & 15) | 16);
            }
            float mu = s * (1.f / DIM), var = ss * (1.f / DIM) - mu * mu;
            float rstd = rsqrtf(var + 1e-5f);
            float nrm = 0.f;
#pragma unroll
            for (int i = 0; i < 8; i++) {
                x[i] = (x[i] - mu) * rstd * g[i] + be[i];
                nrm += x[i] * x[i];
            }
            nrm = wsum(nrm);
            float inv = 1.f / fmaxf(sqrtf(nrm), 1e-12f);
#pragma unroll
            for (int i = 0; i < 4; i++) atomicAdd(&sfacc[rr][4 * lane + i], x[i] * inv);
#pragma unroll
            for (int i = 0; i < 4; i++) atomicAdd(&sfacc[rr][128 + 4 * lane + i], x[4 + i] * inv);
            if (lane == 0) atomicAdd(&scnt[rr], 1);
        }
    }
    __syncthreads();
    for (int t = tid; t < 8 * DIM; t += 256) atomicAdd(&((float*)g_facc)[t], ((float*)sfacc)[t]);
    if (tid < 8) atomicAdd(&g_cnt[tid], scnt[tid]);
}

// ---------------- K_final: EMA update + renormalize prototypes ----------------
__global__ void k_final(float* __restrict__ out) {
    int tid = threadIdx.x;
    int r = tid >> 5, lane = tid & 31;
    float f[8]; float ss = 0.f;
#pragma unroll
    for (int i = 0; i < 8; i++) { f[i] = g_facc[r][lane + 32 * i]; ss += f[i] * f[i]; }
    ss = wsum(ss);
    float inv = 1.f / fmaxf(sqrtf(ss), 1e-12f);
    int c = r >> 1;
    bool cond = ((g_cnt[c * 2] + g_cnt[c * 2 + 1]) > 0) && (g_cnt[r] != 0);
    float u[8]; float ss2 = 0.f;
#pragma unroll
    for (int i = 0; i < 8; i++) {
        float p = g_protos[r][lane + 32 * i];
        u[i] = cond ? (0.999f * p + 0.001f * (f[i] * inv)) : p;
        ss2 += u[i] * u[i];
    }
    ss2 = wsum(ss2);
    float inv2 = 1.f / fmaxf(sqrtf(ss2), 1e-12f);
    float* np = out + OUT_PROTOS;
#pragma unroll
    for (int i = 0; i < 8; i++) np[r * DIM + lane + 32 * i] = u[i] * inv2;
}

// ---------------- launch ----------------
extern "C" void kernel_launch(void* const* d_in, const int* in_sizes, int n_in,
                              void* d_out, int out_size)
{
    const float* feat   = (const float*)d_in[0];
    const int*   label  = (const int*)  d_in[1];
    const float* protos = (const float*)d_in[2];
    const float* fg     = (const float*)d_in[3];
    const float* fb     = (const float*)d_in[4];
    const float* mg     = (const float*)d_in[5];
    const float* mb     = (const float*)d_in[6];
    float* out = (float*)d_out;

    k_init<<<1, 256>>>(protos);
    k_main<<<1184, 256>>>(feat, label, fg, fb, mg, mb, out);
    k_R<<<1184, 256>>>(1);
    k_R<<<1184, 256>>>(2);
    k_target<<<NPIX / 256, 256>>>(out + OUT_TARGET);
    k_accum<<<1184, 256>>>(feat, fg, fb);
    k_final<<<1, 256>>>(out);
}